// round 4
// baseline (speedup 1.0000x reference)
#include <cuda_runtime.h>
#include <cuda_bf16.h>
#include <math.h>
#include <stdint.h>

#define M_TOK 32768
#define DMODEL 1024
#define CD 256
#define NC 4096

#define FLAG_THRESH 1.5e-3f

// ---------------------------------------------------------------------------
// Static device scratch
// ---------------------------------------------------------------------------
__device__ float g_half_norm[NC];
__device__ unsigned short g_x_hi[(size_t)M_TOK * DMODEL];
__device__ unsigned short g_x_lo[(size_t)M_TOK * DMODEL];
__device__ unsigned short g_w_hi[(size_t)CD * DMODEL];   // transposed [n][k]
__device__ unsigned short g_w_lo[(size_t)CD * DMODEL];
__device__ unsigned short g_z_hi[(size_t)M_TOK * CD];
__device__ unsigned short g_cb_hi[(size_t)NC * CD];
__device__ int g_flag_count;
__device__ int g_flag_list[M_TOK];

// ---------------------------------------------------------------------------
// PTX helpers (baseline sm_80-era features: valid on plain sm_103)
// ---------------------------------------------------------------------------
__device__ __forceinline__ uint32_t smem_u32(const void* p) {
    uint32_t a;
    asm("{ .reg .u64 t; cvta.to.shared.u64 t, %1; cvt.u32.u64 %0, t; }" : "=r"(a) : "l"(p));
    return a;
}
__device__ __forceinline__ void cp16(uint32_t dst, const void* src) {
    asm volatile("cp.async.cg.shared.global [%0], [%1], 16;" :: "r"(dst), "l"(src));
}
#define CP_COMMIT() asm volatile("cp.async.commit_group;" ::: "memory")
#define CP_WAIT(n)  asm volatile("cp.async.wait_group %0;" :: "n"(n) : "memory")

#define LDSM4(r0, r1, r2, r3, addr) \
    asm volatile("ldmatrix.sync.aligned.m8n8.x4.shared.b16 {%0,%1,%2,%3}, [%4];" \
                 : "=r"(r0), "=r"(r1), "=r"(r2), "=r"(r3) : "r"(addr))
#define LDSM2(r0, r1, addr) \
    asm volatile("ldmatrix.sync.aligned.m8n8.x2.shared.b16 {%0,%1}, [%2];" \
                 : "=r"(r0), "=r"(r1) : "r"(addr))

#define MMA16816(c, a, b) \
    asm volatile("mma.sync.aligned.m16n8k16.row.col.f32.bf16.bf16.f32 " \
                 "{%0,%1,%2,%3}, {%4,%5,%6,%7}, {%8,%9}, {%0,%1,%2,%3};" \
                 : "+f"((c)[0]), "+f"((c)[1]), "+f"((c)[2]), "+f"((c)[3]) \
                 : "r"((a)[0]), "r"((a)[1]), "r"((a)[2]), "r"((a)[3]), \
                   "r"((b)[0]), "r"((b)[1]))

// ---------------------------------------------------------------------------
// hi/lo bf16 split helpers
// ---------------------------------------------------------------------------
__device__ __forceinline__ void split4(float4 v, uint2& hi, uint2& lo) {
    float f[4] = {v.x, v.y, v.z, v.w};
    unsigned short h[4], l[4];
#pragma unroll
    for (int i = 0; i < 4; i++) {
        __nv_bfloat16 hb = __float2bfloat16(f[i]);
        h[i] = __bfloat16_as_ushort(hb);
        l[i] = __bfloat16_as_ushort(__float2bfloat16(f[i] - __bfloat162float(hb)));
    }
    hi.x = (uint32_t)h[0] | ((uint32_t)h[1] << 16);
    hi.y = (uint32_t)h[2] | ((uint32_t)h[3] << 16);
    lo.x = (uint32_t)l[0] | ((uint32_t)l[1] << 16);
    lo.y = (uint32_t)l[2] | ((uint32_t)l[3] << 16);
}

// ---------------------------------------------------------------------------
// Prep kernels
// ---------------------------------------------------------------------------
__global__ __launch_bounds__(256)
void conv_x_kernel(const float* __restrict__ x) {
    size_t gid = (size_t)blockIdx.x * 256 + threadIdx.x;
    float4 v = *(const float4*)&x[gid * 4];
    uint2 hi, lo; split4(v, hi, lo);
    *(uint2*)&g_x_hi[gid * 4] = hi;
    *(uint2*)&g_x_lo[gid * 4] = lo;
}

__global__ __launch_bounds__(256)
void conv_w_kernel(const float* __restrict__ W) {
    size_t gid = (size_t)blockIdx.x * 256 + threadIdx.x;
    int n = (int)(gid >> 10);
    int k = (int)(gid & 1023);
    float v = W[(size_t)k * CD + n];
    __nv_bfloat16 hb = __float2bfloat16(v);
    g_w_hi[gid] = __bfloat16_as_ushort(hb);
    g_w_lo[gid] = __bfloat16_as_ushort(__float2bfloat16(v - __bfloat162float(hb)));
}

__global__ __launch_bounds__(256)
void conv_z_kernel(const float* __restrict__ z) {
    size_t gid = (size_t)blockIdx.x * 256 + threadIdx.x;   // over M*CD/4
    float4 v = *(const float4*)&z[gid * 4];
    unsigned short h[4];
    float f[4] = {v.x, v.y, v.z, v.w};
#pragma unroll
    for (int i = 0; i < 4; i++) h[i] = __bfloat16_as_ushort(__float2bfloat16(f[i]));
    uint2 hi;
    hi.x = (uint32_t)h[0] | ((uint32_t)h[1] << 16);
    hi.y = (uint32_t)h[2] | ((uint32_t)h[3] << 16);
    *(uint2*)&g_z_hi[gid * 4] = hi;
}

__global__ __launch_bounds__(256)
void conv_cb_kernel(const float* __restrict__ cb) {
    size_t gid = (size_t)blockIdx.x * 256 + threadIdx.x;   // over NC*CD/4
    float4 v = *(const float4*)&cb[gid * 4];
    unsigned short h[4];
    float f[4] = {v.x, v.y, v.z, v.w};
#pragma unroll
    for (int i = 0; i < 4; i++) h[i] = __bfloat16_as_ushort(__float2bfloat16(f[i]));
    uint2 hi;
    hi.x = (uint32_t)h[0] | ((uint32_t)h[1] << 16);
    hi.y = (uint32_t)h[2] | ((uint32_t)h[3] << 16);
    *(uint2*)&g_cb_hi[gid * 4] = hi;
}

__global__ __launch_bounds__(256)
void normalize_kernel(float* __restrict__ z) {
    const int warp = threadIdx.x >> 5;
    const int lane = threadIdx.x & 31;
    const int row  = blockIdx.x * 8 + warp;
    float4* z4 = (float4*)z;
    size_t base = (size_t)row * 64;
    float4 v0 = z4[base + lane];
    float4 v1 = z4[base + 32 + lane];
    float s = v0.x*v0.x + v0.y*v0.y + v0.z*v0.z + v0.w*v0.w
            + v1.x*v1.x + v1.y*v1.y + v1.z*v1.z + v1.w*v1.w;
#pragma unroll
    for (int o = 16; o > 0; o >>= 1) s += __shfl_xor_sync(0xFFFFFFFFu, s, o);
    float inv = 1.0f / (sqrtf(s) + 1e-6f);
    v0.x *= inv; v0.y *= inv; v0.z *= inv; v0.w *= inv;
    v1.x *= inv; v1.y *= inv; v1.z *= inv; v1.w *= inv;
    z4[base + lane]      = v0;
    z4[base + 32 + lane] = v1;
}

__global__ __launch_bounds__(256)
void halfnorm_kernel(const float* __restrict__ cb) {
    const int warp = threadIdx.x >> 5;
    const int lane = threadIdx.x & 31;
    const int code = blockIdx.x * 8 + warp;
    const float4* c4 = (const float4*)cb;
    size_t base = (size_t)code * 64;
    float4 v0 = c4[base + lane];
    float4 v1 = c4[base + 32 + lane];
    float s = v0.x*v0.x + v0.y*v0.y + v0.z*v0.z + v0.w*v0.w
            + v1.x*v1.x + v1.y*v1.y + v1.z*v1.z + v1.w*v1.w;
#pragma unroll
    for (int o = 16; o > 0; o >>= 1) s += __shfl_xor_sync(0xFFFFFFFFu, s, o);
    if (lane == 0) g_half_norm[code] = 0.5f * s;
}

__global__ void reset_kernel() { g_flag_count = 0; }

// ---------------------------------------------------------------------------
// GEMM1 (mma.sync, 3-pass bf16 split) — unchanged from R3 (known good)
// ---------------------------------------------------------------------------
#define G1_SMEM (4 * 18432 + 4 * 18432)

__device__ __forceinline__ void g1_load(uint32_t XS, uint32_t WS, int buf, int kc,
                                        int rowBase, int colBase, int t) {
#pragma unroll
    for (int q = 0; q < 8; q++) {
        int i = t + 256 * q;
        int hl = i >> 10, r = (i >> 3) & 127, cc = i & 7;
        const unsigned short* src = (hl ? g_x_lo : g_x_hi)
            + (size_t)(rowBase + r) * DMODEL + kc * 64 + cc * 8;
        cp16(XS + (buf * 2 + hl) * 18432 + r * 144 + cc * 16, src);
    }
#pragma unroll
    for (int q = 0; q < 8; q++) {
        int i = t + 256 * q;
        int hl = i >> 10, r = (i >> 3) & 127, cc = i & 7;
        const unsigned short* src = (hl ? g_w_lo : g_w_hi)
            + (size_t)(colBase + r) * DMODEL + kc * 64 + cc * 8;
        cp16(WS + (buf * 2 + hl) * 18432 + r * 144 + cc * 16, src);
    }
}

__global__ __launch_bounds__(256, 1)
void gemm1_mma_kernel(const float* __restrict__ bias, float* __restrict__ z) {
    extern __shared__ unsigned char smem[];
    const uint32_t sb = smem_u32(smem);
    const uint32_t XS = sb;
    const uint32_t WS = sb + 4 * 18432;

    const int t = threadIdx.x, lane = t & 31, w = t >> 5;
    const int warpM = w & 1, warpN = w >> 1;
    const int rowBase = blockIdx.x * 128;
    const int colBase = blockIdx.y * 128;

    float acc[4][4][4];
#pragma unroll
    for (int mt = 0; mt < 4; mt++)
#pragma unroll
        for (int nt = 0; nt < 4; nt++)
#pragma unroll
            for (int c = 0; c < 4; c++) acc[mt][nt][c] = 0.0f;

    const uint32_t a_row  = warpM * 64 + (lane & 15);
    const uint32_t a_col8 = (lane >> 4) * 8;
    const uint32_t b_row  = warpN * 32 + (lane & 7);
    const uint32_t b_col8 = ((lane >> 3) & 1) * 8;

    g1_load(XS, WS, 0, 0, rowBase, colBase, t);
    CP_COMMIT();

    for (int kc = 0; kc < 16; kc++) {
        const int buf = kc & 1;
        if (kc + 1 < 16) { g1_load(XS, WS, (kc + 1) & 1, kc + 1, rowBase, colBase, t); CP_COMMIT(); CP_WAIT(1); }
        else             { CP_WAIT(0); }
        __syncthreads();

#pragma unroll
        for (int ks = 0; ks < 4; ks++) {
            uint32_t bh[4][2], bl[4][2];
#pragma unroll
            for (int nt = 0; nt < 4; nt++) {
                uint32_t baddr = WS + (buf * 2) * 18432 + ((b_row + nt * 8) * 72 + ks * 16 + b_col8) * 2;
                LDSM2(bh[nt][0], bh[nt][1], baddr);
                LDSM2(bl[nt][0], bl[nt][1], baddr + 18432);
            }
#pragma unroll
            for (int mt = 0; mt < 4; mt++) {
                uint32_t ah[4], al[4];
                uint32_t aaddr = XS + (buf * 2) * 18432 + ((a_row + mt * 16) * 72 + ks * 16 + a_col8) * 2;
                LDSM4(ah[0], ah[1], ah[2], ah[3], aaddr);
                LDSM4(al[0], al[1], al[2], al[3], aaddr + 18432);
#pragma unroll
                for (int nt = 0; nt < 4; nt++) {
                    MMA16816(acc[mt][nt], ah, bh[nt]);
                    MMA16816(acc[mt][nt], ah, bl[nt]);
                    MMA16816(acc[mt][nt], al, bh[nt]);
                }
            }
        }
        __syncthreads();
    }

    const int row0 = rowBase + warpM * 64 + (lane >> 2);
    const int col0 = colBase + warpN * 32 + (lane & 3) * 2;
#pragma unroll
    for (int mt = 0; mt < 4; mt++) {
#pragma unroll
        for (int nt = 0; nt < 4; nt++) {
            int r0 = row0 + mt * 16;
            int c  = col0 + nt * 8;
            float b0 = __ldg(&bias[c]), b1 = __ldg(&bias[c + 1]);
            *(float2*)&z[(size_t)r0 * CD + c]       = make_float2(acc[mt][nt][0] + b0, acc[mt][nt][1] + b1);
            *(float2*)&z[(size_t)(r0 + 8) * CD + c] = make_float2(acc[mt][nt][2] + b0, acc[mt][nt][3] + b1);
        }
    }
}

// ---------------------------------------------------------------------------
// Quant kernel: 1-pass hi*hi bf16 scores + top-2 margin certification.
// Tokens with margin <= FLAG_THRESH get exact fp32 fixup later.
// smem: z_hi[128][264] (67584B) + cb_hi[2buf][128][72] (36864B) = 104448B
// -> 2 CTAs/SM.
// ---------------------------------------------------------------------------
#define Q_ZBYTES  (128 * 264 * 2)
#define Q_CBBYTES (2 * 18432)
#define Q_SMEM    (Q_ZBYTES + Q_CBBYTES)

// merge top-2 structs (prefer higher val, tie -> lower idx; equal vals from
// different codes make second == best so the token gets flagged)
__device__ __forceinline__ void top2_merge(float& b1, int& i1, float& b2,
                                           float ob1, int oi1, float ob2) {
    if (ob1 > b1)      { b2 = fmaxf(b1, ob2); b1 = ob1; i1 = oi1; }
    else if (ob1 == b1){ if (oi1 != i1) b2 = b1; else b2 = fmaxf(b2, ob2); i1 = min(i1, oi1); }
    else               { b2 = fmaxf(b2, ob1); }
}

__device__ __forceinline__ void q_load_cb(uint32_t CBB, int buf, int tt, int kc, int t) {
#pragma unroll
    for (int q = 0; q < 4; q++) {
        int i = t + 256 * q;
        int r = (i >> 3) & 127, cc = i & 7;
        int code = 1 + tt * 128 + r;
        if (code > NC - 1) code = NC - 1;
        const unsigned short* src = g_cb_hi + (size_t)code * CD + kc * 64 + cc * 8;
        cp16(CBB + buf * 18432 + r * 144 + cc * 16, src);
    }
}

__global__ __launch_bounds__(256, 2)
void quant_mma_kernel(const float* __restrict__ cb,
                      float* __restrict__ out_idx, float* __restrict__ out_hard) {
    extern __shared__ unsigned char smem[];
    const uint32_t sb  = smem_u32(smem);
    const uint32_t ZB  = sb;
    const uint32_t CBB = sb + Q_ZBYTES;

    const int t = threadIdx.x, lane = t & 31, w = t >> 5;
    const int warpM = w & 1, warpN = w >> 1;
    const int rowBase = blockIdx.x * 128;

    // stage z_hi tile, full K=256
#pragma unroll
    for (int q = 0; q < 16; q++) {
        int i = t + 256 * q;
        int r = i >> 5, cc = i & 31;
        const unsigned short* src = g_z_hi + (size_t)(rowBase + r) * CD + cc * 8;
        cp16(ZB + r * 528 + cc * 16, src);
    }
    q_load_cb(CBB, 0, 0, 0, t);
    CP_COMMIT();

    float acc[4][4][4];
#pragma unroll
    for (int mt = 0; mt < 4; mt++)
#pragma unroll
        for (int nt = 0; nt < 4; nt++)
#pragma unroll
            for (int c = 0; c < 4; c++) acc[mt][nt][c] = 0.0f;

    float best[8], sec[8];
    int   bidx[8];
#pragma unroll
    for (int s = 0; s < 8; s++) { best[s] = -3.0e38f; sec[s] = -3.0e38f; bidx[s] = 1; }

    const uint32_t a_row  = warpM * 64 + (lane & 15);
    const uint32_t a_col8 = (lane >> 4) * 8;
    const uint32_t b_row  = warpN * 32 + (lane & 7);
    const uint32_t b_col8 = ((lane >> 3) & 1) * 8;

    for (int it = 0; it < 128; it++) {
        const int tt = it >> 2, kc = it & 3, buf = it & 1;
        if (it + 1 < 128) { q_load_cb(CBB, (it + 1) & 1, (it + 1) >> 2, (it + 1) & 3, t); CP_COMMIT(); CP_WAIT(1); }
        else              { CP_WAIT(0); }
        __syncthreads();

#pragma unroll
        for (int ks = 0; ks < 4; ks++) {
            const int k = kc * 64 + ks * 16;
            uint32_t bh[4][2];
#pragma unroll
            for (int nt = 0; nt < 4; nt++) {
                uint32_t baddr = CBB + buf * 18432 + ((b_row + nt * 8) * 72 + ks * 16 + b_col8) * 2;
                LDSM2(bh[nt][0], bh[nt][1], baddr);
            }
#pragma unroll
            for (int mt = 0; mt < 4; mt++) {
                uint32_t ah[4];
                uint32_t aaddr = ZB + ((a_row + mt * 16) * 264 + k + a_col8) * 2;
                LDSM4(ah[0], ah[1], ah[2], ah[3], aaddr);
#pragma unroll
                for (int nt = 0; nt < 4; nt++)
                    MMA16816(acc[mt][nt], ah, bh[nt]);
            }
        }
        __syncthreads();

        if (kc == 3) {
            const int codeTile = 1 + tt * 128 + warpN * 32;
#pragma unroll
            for (int nt = 0; nt < 4; nt++) {
                int c0 = codeTile + nt * 8 + (lane & 3) * 2;
                float hn0 = (c0 < NC)     ? __ldg(&g_half_norm[c0])     : 0.0f;
                float hn1 = (c0 + 1 < NC) ? __ldg(&g_half_norm[c0 + 1]) : 0.0f;
#pragma unroll
                for (int mt = 0; mt < 4; mt++) {
#pragma unroll
                    for (int h = 0; h < 2; h++) {
                        int s = mt * 2 + h;
                        if (c0 < NC) {
                            float v = acc[mt][nt][h * 2] - hn0;
                            if (v > best[s])      { sec[s] = best[s]; best[s] = v; bidx[s] = c0; }
                            else if (v > sec[s])  { sec[s] = v; }
                        }
                        if (c0 + 1 < NC) {
                            float v = acc[mt][nt][h * 2 + 1] - hn1;
                            if (v > best[s])      { sec[s] = best[s]; best[s] = v; bidx[s] = c0 + 1; }
                            else if (v > sec[s])  { sec[s] = v; }
                        }
                    }
                    acc[mt][nt][0] = 0.0f; acc[mt][nt][1] = 0.0f;
                    acc[mt][nt][2] = 0.0f; acc[mt][nt][3] = 0.0f;
                }
            }
        }
    }

    // reduce across lanes (xor 1, 2) then across warpN via smem
    float* red_val = (float*)(smem + Q_ZBYTES);
    float* red_sec = (float*)(smem + Q_ZBYTES + 2048);
    int*   red_idx = (int*)(smem + Q_ZBYTES + 4096);
    int*   row_idx = (int*)(smem + Q_ZBYTES + 6144);

#pragma unroll
    for (int slot = 0; slot < 8; slot++) {
        float b1 = best[slot], b2 = sec[slot]; int i1 = bidx[slot];
#pragma unroll
        for (int off = 1; off <= 2; off <<= 1) {
            float ob1 = __shfl_xor_sync(0xFFFFFFFFu, b1, off);
            int   oi1 = __shfl_xor_sync(0xFFFFFFFFu, i1, off);
            float ob2 = __shfl_xor_sync(0xFFFFFFFFu, b2, off);
            top2_merge(b1, i1, b2, ob1, oi1, ob2);
        }
        if ((lane & 3) == 0) {
            int mt = slot >> 1, h = slot & 1;
            int row = warpM * 64 + mt * 16 + (lane >> 2) + h * 8;
            red_val[row * 4 + warpN] = b1;
            red_sec[row * 4 + warpN] = b2;
            red_idx[row * 4 + warpN] = i1;
        }
    }
    __syncthreads();

    if (t < 128) {
        float b1 = red_val[t * 4], b2 = red_sec[t * 4];
        int i1 = red_idx[t * 4];
#pragma unroll
        for (int q = 1; q < 4; q++)
            top2_merge(b1, i1, b2, red_val[t * 4 + q], red_idx[t * 4 + q], red_sec[t * 4 + q]);
        row_idx[t] = i1;
        out_idx[rowBase + t] = (float)i1;
        if (b1 - b2 <= FLAG_THRESH) {
            int pos = atomicAdd(&g_flag_count, 1);
            g_flag_list[pos] = rowBase + t;
        }
    }
    __syncthreads();

    for (int r = 0; r < 128; r++) {
        int code = row_idx[r];
        out_hard[(size_t)(rowBase + r) * CD + t] = __ldg(&cb[(size_t)code * CD + t]);
    }
}

// ---------------------------------------------------------------------------
// Fixup: exact fp32 argmin over all codes for flagged tokens.
// One block per flagged token (strided). z row staged in smem.
// ---------------------------------------------------------------------------
__global__ __launch_bounds__(256)
void fixup_kernel(const float* __restrict__ z, const float* __restrict__ cb,
                  float* __restrict__ out_idx, float* __restrict__ out_hard) {
    __shared__ float zs[CD];
    __shared__ float rv[8];
    __shared__ int   ri[8];
    __shared__ int   s_best;

    const int t = threadIdx.x, lane = t & 31, warp = t >> 5;
    const int count = g_flag_count;

    for (int i = blockIdx.x; i < count; i += gridDim.x) {
        const int token = g_flag_list[i];
        zs[t] = z[(size_t)token * CD + t];
        __syncthreads();

        float bv = -3.0e38f; int bi = 1;
        for (int j = 0; j < 16; j++) {
            int code = 1 + t + 256 * j;
            if (code >= NC) break;
            const float4* c4 = (const float4*)&cb[(size_t)code * CD];
            float s = 0.0f;
#pragma unroll
            for (int k = 0; k < 64; k++) {
                float4 cv = c4[k];
                s += zs[k * 4 + 0] * cv.x + zs[k * 4 + 1] * cv.y
                   + zs[k * 4 + 2] * cv.z + zs[k * 4 + 3] * cv.w;
            }
            s -= __ldg(&g_half_norm[code]);
            if (s > bv || (s == bv && code < bi)) { bv = s; bi = code; }
        }
#pragma unroll
        for (int off = 16; off > 0; off >>= 1) {
            float ov = __shfl_xor_sync(0xFFFFFFFFu, bv, off);
            int   oi = __shfl_xor_sync(0xFFFFFFFFu, bi, off);
            if (ov > bv || (ov == bv && oi < bi)) { bv = ov; bi = oi; }
        }
        if (lane == 0) { rv[warp] = bv; ri[warp] = bi; }
        __syncthreads();
        if (t == 0) {
            float fbv = rv[0]; int fbi = ri[0];
#pragma unroll
            for (int q = 1; q < 8; q++)
                if (rv[q] > fbv || (rv[q] == fbv && ri[q] < fbi)) { fbv = rv[q]; fbi = ri[q]; }
            s_best = fbi;
            out_idx[token] = (float)fbi;
        }
        __syncthreads();
        int code = s_best;
        out_hard[(size_t)token * CD + t] = __ldg(&cb[(size_t)code * CD + t]);
        __syncthreads();
    }
}

// ---------------------------------------------------------------------------
// Launch
// ---------------------------------------------------------------------------
extern "C" void kernel_launch(void* const* d_in, const int* in_sizes, int n_in,
                              void* d_out, int out_size) {
    const float* x  = (const float*)d_in[0];   // [32768, 1024]
    const float* cb = (const float*)d_in[1];   // [4096, 256]
    const float* W  = (const float*)d_in[2];   // [1024, 256]
    const float* b  = (const float*)d_in[3];   // [256]

    float* out   = (float*)d_out;
    float* z     = out;                              // [32768, 256]
    float* oidx  = out + (size_t)M_TOK * CD;         // [32768]
    float* ohard = oidx + M_TOK;                     // [32768, 256]

    cudaFuncSetAttribute(gemm1_mma_kernel, cudaFuncAttributeMaxDynamicSharedMemorySize, G1_SMEM);
    cudaFuncSetAttribute(quant_mma_kernel, cudaFuncAttributeMaxDynamicSharedMemorySize, Q_SMEM);

    reset_kernel<<<1, 1>>>();
    conv_x_kernel<<<(int)((size_t)M_TOK * DMODEL / 4 / 256), 256>>>(x);
    conv_w_kernel<<<(CD * DMODEL) / 256, 256>>>(W);
    halfnorm_kernel<<<NC / 8, 256>>>(cb);
    conv_cb_kernel<<<(NC * CD / 4) / 256, 256>>>(cb);

    gemm1_mma_kernel<<<dim3(M_TOK / 128, CD / 128), 256, G1_SMEM>>>(b, z);
    normalize_kernel<<<M_TOK / 8, 256>>>(z);
    conv_z_kernel<<<(M_TOK * CD / 4) / 256, 256>>>(z);

    quant_mma_kernel<<<M_TOK / 128, 256, Q_SMEM>>>(cb, oidx, ohard);
    fixup_kernel<<<1024, 256>>>(z, cb, oidx, ohard);
}